// round 8
// baseline (speedup 1.0000x reference)
#include <cuda_runtime.h>
#include <math.h>

// GATNET: N=20000, E=640000, IN=256, H=4, OUT=64
#define NN   20000
#define EE   640000
#define ET   (EE + NN)
#define KIN  256
#define HC   256
#define H1   4
#define C1   64
#define C2   64

__device__ float g_h1[NN * HC];
__device__ float g_x1[NN * HC];
__device__ float g_h2[NN * C2];
__device__ float g_as1[NN * H1];
__device__ float g_ad1[NN * H1];
__device__ float g_as2[NN];
__device__ float g_ad2[NN];
__device__ int   g_cnt[NN];
__device__ int   g_ptr[NN + 1];
__device__ int   g_cur[NN];
__device__ int   g_csr_src[ET];
__device__ float g_w1c[ET * H1];
__device__ float g_w2c[ET];
__device__ int   g_is64;

// ---------------- edge dtype probe (verified: int32; kept as insurance) ----------------
__global__ void detect_k(const long long* __restrict__ ei64) {
    __shared__ int bad;
    if (threadIdx.x == 0) bad = 0;
    __syncthreads();
    for (int i = threadIdx.x; i < 2048; i += blockDim.x) {
        long long v = ei64[i];
        if (v < 0 || v >= NN) bad = 1;
    }
    __syncthreads();
    if (threadIdx.x == 0) g_is64 = bad ? 0 : 1;
}

__device__ __forceinline__ void load_edge(const void* __restrict__ ei, int e, int& s, int& d) {
    if (e >= EE) { s = d = e - EE; return; }
    if (g_is64) {
        const long long* p = (const long long*)ei;
        s = (int)p[e]; d = (int)p[EE + e];
    } else {
        const int* p = (const int*)ei;
        s = p[e]; d = p[EE + e];
    }
}

// ---------------- CSR build ----------------
__global__ void zcnt_k() {
    int t = blockIdx.x * blockDim.x + threadIdx.x;
    if (t < NN) g_cnt[t] = 0;
}

__global__ void count_k(const void* __restrict__ ei) {
    int e = blockIdx.x * blockDim.x + threadIdx.x;
    if (e >= ET) return;
    int s, d; load_edge(ei, e, s, d);
    if ((unsigned)d < NN) atomicAdd(&g_cnt[d], 1);
}

__global__ __launch_bounds__(1024) void scan_k() {
    __shared__ int buf[1024];
    __shared__ int carry;
    if (threadIdx.x == 0) carry = 0;
    __syncthreads();
    for (int base = 0; base < NN; base += 1024) {
        int i = base + threadIdx.x;
        int v = (i < NN) ? g_cnt[i] : 0;
        buf[threadIdx.x] = v;
        __syncthreads();
        for (int off = 1; off < 1024; off <<= 1) {
            int t = (threadIdx.x >= off) ? buf[threadIdx.x - off] : 0;
            __syncthreads();
            buf[threadIdx.x] += t;
            __syncthreads();
        }
        int excl = buf[threadIdx.x] - v;
        if (i < NN) { g_ptr[i] = carry + excl; g_cur[i] = carry + excl; }
        __syncthreads();
        if (threadIdx.x == 1023) carry += buf[1023];
        __syncthreads();
    }
    if (threadIdx.x == 0) g_ptr[NN] = carry;
}

__global__ void scatter_k(const void* __restrict__ ei) {
    int e = blockIdx.x * blockDim.x + threadIdx.x;
    if (e >= ET) return;
    int s, d; load_edge(ei, e, s, d);
    if ((unsigned)d < NN && (unsigned)s < NN) {
        int pos = atomicAdd(&g_cur[d], 1);
        g_csr_src[pos] = s;
    }
}

// ---------------- tiled SGEMM: C[M,N] = A[M,K] @ B[K,N] ----------------
__global__ __launch_bounds__(256) void sgemm_k(const float* __restrict__ A,
                                               const float* __restrict__ B,
                                               float* __restrict__ C,
                                               int M, int N, int K) {
    __shared__ float As[16][68];
    __shared__ float Bs[16][64];
    const int bn = blockIdx.x * 64;
    const int bm = blockIdx.y * 64;
    const int tid = threadIdx.x;
    const int tx = tid & 15, ty = tid >> 4;
    const int la_k = tid & 15, la_m = tid >> 4;
    const int lb_c = tid & 63, lb_k = tid >> 6;
    float acc[4][4] = {};

    for (int k0 = 0; k0 < K; k0 += 16) {
#pragma unroll
        for (int i = 0; i < 4; i++) {
            int m = la_m + i * 16;
            int gm = bm + m;
            As[la_k][m] = (gm < M) ? A[(size_t)gm * K + k0 + la_k] : 0.0f;
        }
#pragma unroll
        for (int i = 0; i < 4; i++) {
            int kk = lb_k + i * 4;
            Bs[kk][lb_c] = B[(size_t)(k0 + kk) * N + bn + lb_c];
        }
        __syncthreads();
#pragma unroll
        for (int k = 0; k < 16; k++) {
            float4 a4 = *(const float4*)&As[k][ty * 4];
            float4 b4 = *(const float4*)&Bs[k][tx * 4];
            float av[4] = {a4.x, a4.y, a4.z, a4.w};
            float bv[4] = {b4.x, b4.y, b4.z, b4.w};
#pragma unroll
            for (int i = 0; i < 4; i++)
#pragma unroll
                for (int j = 0; j < 4; j++) acc[i][j] += av[i] * bv[j];
        }
        __syncthreads();
    }
#pragma unroll
    for (int i = 0; i < 4; i++) {
        int gm = bm + ty * 4 + i;
        if (gm < M)
#pragma unroll
            for (int j = 0; j < 4; j++)
                C[(size_t)gm * N + bn + tx * 4 + j] = acc[i][j];
    }
}

// ---------------- attention logits ----------------
__global__ void att1_k(const float* __restrict__ att_src, const float* __restrict__ att_dst) {
    int t = blockIdx.x * blockDim.x + threadIdx.x;
    if (t >= NN * H1) return;
    int n = t / H1, h = t % H1;
    const float* row = g_h1 + (size_t)n * HC + h * C1;
    const float* asv = att_src + h * C1;
    const float* adv = att_dst + h * C1;
    float s = 0.f, d = 0.f;
#pragma unroll 8
    for (int c = 0; c < C1; c++) { float v = row[c]; s += v * asv[c]; d += v * adv[c]; }
    g_as1[t] = s; g_ad1[t] = d;
}

__global__ void att2_k(const float* __restrict__ att_src, const float* __restrict__ att_dst) {
    int n = blockIdx.x * blockDim.x + threadIdx.x;
    if (n >= NN) return;
    const float* row = g_h2 + (size_t)n * C2;
    float s = 0.f, d = 0.f;
#pragma unroll 8
    for (int c = 0; c < C2; c++) { float v = row[c]; s += v * att_src[c]; d += v * att_dst[c]; }
    g_as2[n] = s; g_ad2[n] = d;
}

// ---------------- fused edge-softmax + gather, layer 1 ----------------
__global__ __launch_bounds__(256) void gat1_k(const float* __restrict__ bias1) {
    const int d = blockIdx.x;
    const int tid = threadIdx.x;
    const int p0 = g_ptr[d], p1 = g_ptr[d + 1];
    const int cnt = p1 - p0;

    float loc[H1] = {0.f, 0.f, 0.f, 0.f};
    const int items = cnt * H1;
    for (int i = tid; i < items; i += 256) {
        int j = p0 + (i >> 2);
        int h = i & 3;
        int s = g_csr_src[j];
        float x = g_as1[s * H1 + h] + g_ad1[d * H1 + h];
        x = (x > 0.f) ? x : 0.2f * x;
        x = fmaxf(x, -60.f);
        float w = expf(x);
        g_w1c[j * H1 + h] = w;
        loc[h] += w;
    }
#pragma unroll
    for (int h = 0; h < H1; h++)
#pragma unroll
        for (int o = 16; o; o >>= 1) loc[h] += __shfl_down_sync(0xffffffffu, loc[h], o);
    __shared__ float sw[8][H1];
    if ((tid & 31) == 0)
#pragma unroll
        for (int h = 0; h < H1; h++) sw[tid >> 5][h] = loc[h];
    __syncthreads();
    __shared__ float sinv[H1];
    if (tid < H1) {
        float s = 0.f;
#pragma unroll
        for (int w = 0; w < 8; w++) s += sw[w][tid];
        sinv[tid] = 1.0f / (s + 1e-16f);
    }
    __syncthreads();

    const int f = tid, h = f >> 6;
    const float inv = sinv[h];
    float acc = 0.f;
    for (int j = p0; j < p1; j++) {
        int s = g_csr_src[j];
        acc += g_w1c[j * H1 + h] * g_h1[(size_t)s * HC + f];
    }
    float v = acc * inv + bias1[f];
    g_x1[(size_t)d * HC + f] = (v > 0.f) ? v : expm1f(v);   // ELU
}

// ---------------- fused edge-softmax + gather, layer 2 ----------------
__global__ __launch_bounds__(64) void gat2_k(const float* __restrict__ bias2,
                                             float* __restrict__ out) {
    const int d = blockIdx.x;
    const int tid = threadIdx.x;
    const int p0 = g_ptr[d], p1 = g_ptr[d + 1];
    const int cnt = p1 - p0;

    float loc = 0.f;
    const float ad = g_ad2[d];
    for (int i = tid; i < cnt; i += 64) {
        int j = p0 + i;
        int s = g_csr_src[j];
        float x = g_as2[s] + ad;
        x = (x > 0.f) ? x : 0.2f * x;
        x = fmaxf(x, -60.f);
        float w = expf(x);
        g_w2c[j] = w;
        loc += w;
    }
#pragma unroll
    for (int o = 16; o; o >>= 1) loc += __shfl_down_sync(0xffffffffu, loc, o);
    __shared__ float sw2[2];
    if ((tid & 31) == 0) sw2[tid >> 5] = loc;
    __syncthreads();
    __shared__ float sinv2;
    if (tid == 0) sinv2 = 1.0f / (sw2[0] + sw2[1] + 1e-16f);
    __syncthreads();

    const int f = tid;
    const float inv = sinv2;
    float acc = 0.f;
    for (int j = p0; j < p1; j++) {
        int s = g_csr_src[j];
        acc += g_w2c[j] * g_h2[(size_t)s * C2 + f];
    }
    out[(size_t)d * C2 + f] = acc * inv + bias2[f];
}

// ---------------- launch ----------------
extern "C" void kernel_launch(void* const* d_in, const int* in_sizes, int n_in,
                              void* d_out, int out_size) {
    // Verified layout (R7 dump): element counts, declared order, int32 edges.
    const float* x   = (const float*)d_in[0];
    const void*  ei  = d_in[1];
    const float* W1  = (const float*)d_in[2];
    const float* as1 = (const float*)d_in[3];
    const float* ad1 = (const float*)d_in[4];
    const float* b1  = (const float*)d_in[5];
    const float* W2  = (const float*)d_in[6];
    const float* as2 = (const float*)d_in[7];
    const float* ad2 = (const float*)d_in[8];
    const float* b2  = (const float*)d_in[9];
    float* out = (float*)d_out;

    // CRITICAL (R7 root cause): __device__ symbols passed as kernel args from
    // host code resolve to the HOST shadow address (silently writable on GB300
    // via ATS). Must resolve the true device address via cudaGetSymbolAddress.
    float *h1p = nullptr, *x1p = nullptr, *h2p = nullptr;
    cudaGetSymbolAddress((void**)&h1p, g_h1);
    cudaGetSymbolAddress((void**)&x1p, g_x1);
    cudaGetSymbolAddress((void**)&h2p, g_h2);

    detect_k<<<1, 256>>>((const long long*)ei);

    // CSR by dst
    zcnt_k<<<(NN + 255) / 256, 256>>>();
    count_k<<<(ET + 255) / 256, 256>>>(ei);
    scan_k<<<1, 1024>>>();
    scatter_k<<<(ET + 255) / 256, 256>>>(ei);

    // layer 1
    { dim3 g(HC / 64, (NN + 63) / 64); sgemm_k<<<g, 256>>>(x, W1, h1p, NN, HC, KIN); }
    att1_k<<<(NN * H1 + 255) / 256, 256>>>(as1, ad1);
    gat1_k<<<NN, 256>>>(b1);

    // layer 2
    { dim3 g(C2 / 64, (NN + 63) / 64); sgemm_k<<<g, 256>>>(x1p, W2, h2p, NN, C2, HC); }
    att2_k<<<(NN + 255) / 256, 256>>>(as2, ad2);
    gat2_k<<<NN, 64>>>(b2, out);
}